// round 11
// baseline (speedup 1.0000x reference)
#include <cuda_runtime.h>

typedef unsigned long long ull;

// Problem constants
#define LSEQ 512
#define NH 12
#define FD 16
#define HD 64
#define DM 768
#define DREAL 273
#define DP 288          // padded feature dim (zeros in 273..287)
#define CH 8            // number of chunks
#define CT 64           // chunk length
#define PROJ_N 1152     // q(192) | k(192) | v(768)
#define EPSV 1e-12f
#define PHI_S 0.17677669529663687f   // 1/(4*sqrt(2))

// Scratch (device globals; no allocation allowed)
__device__ float g_P[LSEQ * PROJ_N];            // projection output
__device__ float g_phiQ[NH * LSEQ * DP];
__device__ float g_phiK[NH * LSEQ * DP];
__device__ float g_S[NH * CH * DP * HD];        // chunk KV sums -> exclusive prefix states
__device__ float g_Z[NH * CH * DP];             // chunk k sums  -> exclusive prefix
__device__ float g_Y[LSEQ * DM];                // attention output (pre-Wo)

// ---------------------------------------------------------------------------
// Packed f32x2 helpers
// ---------------------------------------------------------------------------
__device__ __forceinline__ ull dup2(float a) {
    ull r; asm("mov.b64 %0, {%1, %1};" : "=l"(r) : "f"(a)); return r;
}
__device__ __forceinline__ void fma2(ull& d, ull a, ull b) {
    asm("fma.rn.f32x2 %0, %1, %2, %0;" : "+l"(d) : "l"(a), "l"(b));
}
__device__ __forceinline__ float2 unpk(ull v) {
    float2 r; asm("mov.b64 {%0, %1}, %2;" : "=f"(r.x), "=f"(r.y) : "l"(v)); return r;
}

// ---------------------------------------------------------------------------
// Tiled fp32 GEMM: C[row0+m, coff+n] = sum_k A[row0+m,k] * B[n,k]
// BM=BN=64, BK=16, 256 threads, 4x4 micro-tile (R4-proven version).
// A operand stored DUPLICATED in smem so FFMA2 needs no broadcast movs.
// ---------------------------------------------------------------------------
__device__ __forceinline__ void gemm_body(
    const float* __restrict__ A, const float* __restrict__ B,
    float* __restrict__ C, int K, int ldc, int coff, int row0)
{
    __shared__ __align__(16) float As2[2][16][132];   // [k][2*row] duplicated pairs
    __shared__ __align__(16) float Bs[2][16][68];
    const int tid = threadIdx.x;
    const int tx = tid & 15, ty = tid >> 4;
    const int ty8 = ty * 8, tx4 = tx * 4;
    const int lr = tid >> 2;            // 0..63
    const int lk = (tid & 3) * 4;       // 0,4,8,12

    ull acc[4][2];
#pragma unroll
    for (int i = 0; i < 4; i++) { acc[i][0] = 0ull; acc[i][1] = 0ull; }

    const float* ap = &A[(size_t)(row0 + lr) * K + lk];
    const float* bp = &B[(size_t)lr * K + lk];

    {
        float4 av = *(const float4*)ap;
        float4 bv = *(const float4*)bp;
        *(float2*)&As2[0][lk + 0][2 * lr] = make_float2(av.x, av.x);
        *(float2*)&As2[0][lk + 1][2 * lr] = make_float2(av.y, av.y);
        *(float2*)&As2[0][lk + 2][2 * lr] = make_float2(av.z, av.z);
        *(float2*)&As2[0][lk + 3][2 * lr] = make_float2(av.w, av.w);
        Bs[0][lk + 0][lr] = bv.x; Bs[0][lk + 1][lr] = bv.y;
        Bs[0][lk + 2][lr] = bv.z; Bs[0][lk + 3][lr] = bv.w;
    }
    __syncthreads();

    int buf = 0;
    for (int k0 = 0; k0 < K; k0 += 16) {
        float4 av2, bv2;
        const bool more = (k0 + 16 < K);
        if (more) {
            av2 = *(const float4*)(ap + k0 + 16);
            bv2 = *(const float4*)(bp + k0 + 16);
        }
#pragma unroll
        for (int kk = 0; kk < 16; kk++) {
            ulonglong2 aP = *(const ulonglong2*)&As2[buf][kk][ty8];
            ulonglong2 aQ = *(const ulonglong2*)&As2[buf][kk][ty8 + 4];
            ulonglong2 b  = *(const ulonglong2*)&Bs[buf][kk][tx4];
            fma2(acc[0][0], aP.x, b.x); fma2(acc[0][1], aP.x, b.y);
            fma2(acc[1][0], aP.y, b.x); fma2(acc[1][1], aP.y, b.y);
            fma2(acc[2][0], aQ.x, b.x); fma2(acc[2][1], aQ.x, b.y);
            fma2(acc[3][0], aQ.y, b.x); fma2(acc[3][1], aQ.y, b.y);
        }
        if (more) {
            const int nb = buf ^ 1;
            *(float2*)&As2[nb][lk + 0][2 * lr] = make_float2(av2.x, av2.x);
            *(float2*)&As2[nb][lk + 1][2 * lr] = make_float2(av2.y, av2.y);
            *(float2*)&As2[nb][lk + 2][2 * lr] = make_float2(av2.z, av2.z);
            *(float2*)&As2[nb][lk + 3][2 * lr] = make_float2(av2.w, av2.w);
            Bs[nb][lk + 0][lr] = bv2.x; Bs[nb][lk + 1][lr] = bv2.y;
            Bs[nb][lk + 2][lr] = bv2.z; Bs[nb][lk + 3][lr] = bv2.w;
        }
        __syncthreads();
        buf ^= 1;
    }

#pragma unroll
    for (int i = 0; i < 4; i++) {
        float2 p0 = unpk(acc[i][0]);
        float2 p1 = unpk(acc[i][1]);
        float4 o; o.x = p0.x; o.y = p0.y; o.z = p1.x; o.w = p1.y;
        *(float4*)&C[(size_t)(row0 + ty * 4 + i) * ldc + coff + tx4] = o;
    }
}

// Fused q|k|v projection: grid (8, 18)
__global__ __launch_bounds__(256) void gemm_proj_fused(
    const float* __restrict__ hs, const float* __restrict__ Wq,
    const float* __restrict__ Wk, const float* __restrict__ Wv)
{
    const int cb = blockIdx.y;
    const float* B; int coff;
    if (cb < 3)      { B = Wq + (size_t)cb * 64 * DM;        coff = cb * 64; }
    else if (cb < 6) { B = Wk + (size_t)(cb - 3) * 64 * DM;  coff = 192 + (cb - 3) * 64; }
    else             { B = Wv + (size_t)(cb - 6) * 64 * DM;  coff = 384 + (cb - 6) * 64; }
    gemm_body(hs, B, g_P, DM, PROJ_N, coff, blockIdx.x * 64);
}

// Output projection: grid (8, 12)
__global__ __launch_bounds__(256) void gemm_out_kernel(
    const float* __restrict__ Wo, float* __restrict__ out)
{
    gemm_body(g_Y, Wo + (size_t)blockIdx.y * 64 * DM, out, DM, DM,
              blockIdx.y * 64, blockIdx.x * 64);
}

// ---------------------------------------------------------------------------
// Taylor feature map: phi = [1, x/2, x_i*x_j/(4*sqrt(2))], padded with zeros.
// grid (512), 288 threads — each block handles one sequence position, all heads
// ---------------------------------------------------------------------------
__global__ void phi_kernel()
{
    const int l = blockIdx.x, d = threadIdx.x;
    __shared__ float sx[384];
    for (int i = d; i < 384; i += 288) sx[i] = g_P[(size_t)l * PROJ_N + i];
    __syncthreads();

    int ii = 0, jj = 0, mode;
    if (d == 0) mode = 0;
    else if (d <= 16) { mode = 1; ii = d - 1; }
    else if (d < DREAL) { mode = 2; const int e = d - 17; ii = e >> 4; jj = e & 15; }
    else mode = 3;

    const size_t base = (size_t)l * DP + d;
#pragma unroll
    for (int h = 0; h < NH; h++) {
        const float* xq = &sx[h * FD];
        const float* xk = &sx[192 + h * FD];
        float vq, vk;
        if (mode == 0)      { vq = 1.f; vk = 1.f; }
        else if (mode == 1) { vq = xq[ii] * 0.5f; vk = xk[ii] * 0.5f; }
        else if (mode == 2) { vq = xq[ii] * xq[jj] * PHI_S; vk = xk[ii] * xk[jj] * PHI_S; }
        else                { vq = 0.f; vk = 0.f; }
        g_phiQ[(size_t)h * LSEQ * DP + base] = vq;
        g_phiK[(size_t)h * LSEQ * DP + base] = vk;
    }
}

// ---------------------------------------------------------------------------
// Per-chunk local sums: S_local[d][j] = sum_t phiK[t][d]*V[t][j]; z[d]=sum_t phiK
// grid (CH, NH), 288 threads (one per feature d), packed FFMA2
// ---------------------------------------------------------------------------
__global__ void chunk_kv_kernel()
{
    const int c = blockIdx.x, h = blockIdx.y;
    __shared__ __align__(16) float sV[CT][68];
    const int tid = threadIdx.x;
    for (int idx = tid; idx < CT * HD; idx += 288) {
        const int t = idx >> 6, j = idx & 63;
        sV[t][j] = g_P[(size_t)(c * CT + t) * PROJ_N + 384 + h * HD + j];
    }
    __syncthreads();

    const int d = tid;      // 0..287
    ull acc[32];
#pragma unroll
    for (int i = 0; i < 32; i++) acc[i] = 0ull;
    float zs = 0.f;

    const float* pk = &g_phiK[(size_t)(h * LSEQ + c * CT) * DP + d];
#pragma unroll 2
    for (int t = 0; t < CT; t++) {
        const float kd = pk[(size_t)t * DP];
        zs += kd;
        const ull kdp = dup2(kd);
#pragma unroll
        for (int j = 0; j < 16; j++) {
            ulonglong2 v = *(const ulonglong2*)&sV[t][j * 4];
            fma2(acc[2 * j + 0], kdp, v.x);
            fma2(acc[2 * j + 1], kdp, v.y);
        }
    }
    float* outp = &g_S[((size_t)(h * CH + c) * DP + d) * HD];
#pragma unroll
    for (int j = 0; j < 16; j++) {
        float2 p0 = unpk(acc[2 * j + 0]);
        float2 p1 = unpk(acc[2 * j + 1]);
        float4 o; o.x = p0.x; o.y = p0.y; o.z = p1.x; o.w = p1.y;
        *(float4*)&outp[j * 4] = o;
    }
    g_Z[(size_t)(h * CH + c) * DP + d] = zs;
}

// ---------------------------------------------------------------------------
// Merged parallel exclusive prefix over chunks (S lanes then Z lanes).
// ---------------------------------------------------------------------------
#define NSLANE (NH * DP * HD)
#define NZLANE (NH * DP)
__global__ __launch_bounds__(256) void prefix_kernel()
{
    const int idx = blockIdx.x * 256 + threadIdx.x;
    if (idx < NSLANE) {
        const int h = idx / (DP * HD);
        const int r = idx - h * (DP * HD);
        const size_t base = (size_t)h * CH * DP * HD + r;
        float v[CH];
#pragma unroll
        for (int c = 0; c < CH; c++) v[c] = g_S[base + (size_t)c * DP * HD];
        float carry = 0.f;
#pragma unroll
        for (int c = 0; c < CH; c++) {
            g_S[base + (size_t)c * DP * HD] = carry;
            carry += v[c];
        }
    } else if (idx < NSLANE + NZLANE) {
        const int z = idx - NSLANE;
        const int h = z / DP;
        const int d = z - h * DP;
        const size_t base = (size_t)h * CH * DP + d;
        float v[CH];
#pragma unroll
        for (int c = 0; c < CH; c++) v[c] = g_Z[base + (size_t)c * DP];
        float carry = 0.f;
#pragma unroll
        for (int c = 0; c < CH; c++) {
            g_Z[base + (size_t)c * DP] = carry;
            carry += v[c];
        }
    }
}

// ---------------------------------------------------------------------------
// Per-chunk attention output, ROW-SPLIT with 256 threads: grid (CH, NH, 2).
// Each block computes 32 rows: A[32x64]=tril(phiQ phiK^T), Y=phiQ@S + A@V,
// den = phiQ.z + rowsum(A) + eps. Microtile 2x4 per thread (16x16 layout).
// phi read from global (materialized), register-prefetched per tile.
// ---------------------------------------------------------------------------
__global__ __launch_bounds__(256) void attn_out_kernel()
{
    const int c = blockIdx.x, h = blockIdx.y;
    const int rbase = blockIdx.z * 32;
    __shared__ __align__(16) float sAd[32][132];      // masked A rows, duplicated pairs
    __shared__ __align__(16) float sV[CT][68];
    __shared__ __align__(16) float sQt2[16][68];      // phi(q) [feat][2*row(32)] dup
    __shared__ __align__(16) float sKt[16][68];       // phi(k) [feat][row(64)]
    __shared__ __align__(16) float sS[16][68];
    __shared__ float sZ[16];
    __shared__ float sDen[32];

    const int tid = threadIdx.x;
    const int tx = tid & 15, ty = tid >> 4;           // ty 0..15 -> rows 2*ty..2*ty+1
    const int ty2 = ty * 2, tx4 = tx * 4;

    // load V chunk
    for (int idx = tid; idx < CT * HD; idx += 256) {
        const int t = idx >> 6, j = idx & 63;
        sV[t][j] = g_P[(size_t)(c * CT + t) * PROJ_N + 384 + h * HD + j];
    }

    const float* phq = &g_phiQ[(size_t)(h * LSEQ + c * CT + rbase) * DP];
    const float* phk = &g_phiK[(size_t)(h * LSEQ + c * CT) * DP];
    const float* Sp = &g_S[(size_t)(h * CH + c) * DP * HD];
    const float* Zp = &g_Z[(size_t)(h * CH + c) * DP];

    ull accA[2][2], accY[2][2];
    accA[0][0] = accA[0][1] = accA[1][0] = accA[1][1] = 0ull;
    accY[0][0] = accY[0][1] = accY[1][0] = accY[1][1] = 0ull;
    float den0 = 0.f, den1 = 0.f;

    // lane mappings for tile fills
    const int qrow = tid >> 2, qf = (tid & 3) * 4;    // phiQ: tid<128 -> 32 rows x 4 f4
    const int krow = tid >> 2, kf = (tid & 3) * 4;    // phiK: 64 rows x 4 f4 (all 256)
    const int sd = tid >> 4, sj = (tid & 15) * 4;     // S: 16 feats x 16 j4

    // prefetch tile 0
    float4 qv, kv, sv;
    if (tid < 128) qv = *(const float4*)&phq[(size_t)qrow * DP + qf];
    kv = *(const float4*)&phk[(size_t)krow * DP + kf];
    sv = *(const float4*)&Sp[(size_t)sd * HD + sj];
    float zv = (tid < 16) ? Zp[tid] : 0.f;

    for (int d0 = 0; d0 < DP; d0 += 16) {
        // commit current tile to smem
        if (tid < 128) {
            *(float2*)&sQt2[qf + 0][2 * qrow] = make_float2(qv.x, qv.x);
            *(float2*)&sQt2[qf + 1][2 * qrow] = make_float2(qv.y, qv.y);
            *(float2*)&sQt2[qf + 2][2 * qrow] = make_float2(qv.z, qv.z);
            *(float2*)&sQt2[qf + 3][2 * qrow] = make_float2(qv.w, qv.w);
        }
        sKt[kf + 0][krow] = kv.x; sKt[kf + 1][krow] = kv.y;
        sKt[kf + 2][krow] = kv.z; sKt[kf + 3][krow] = kv.w;
        *(float4*)&sS[sd][sj] = sv;
        if (tid < 16) sZ[tid] = zv;
        __syncthreads();

        // prefetch next tile
        const int dn = d0 + 16;
        if (dn < DP) {
            if (tid < 128) qv = *(const float4*)&phq[(size_t)qrow * DP + dn + qf];
            kv = *(const float4*)&phk[(size_t)krow * DP + dn + kf];
            sv = *(const float4*)&Sp[(size_t)(dn + sd) * HD + sj];
            if (tid < 16) zv = Zp[dn + tid];
        }

#pragma unroll
        for (int dd = 0; dd < 16; dd++) {
            ulonglong2 aP = *(const ulonglong2*)&sQt2[dd][4 * ty];   // (r0,r0),(r1,r1)
            ulonglong2 kp = *(const ulonglong2*)&sKt[dd][tx4];
            ulonglong2 sp = *(const ulonglong2*)&sS[dd][tx4];
            fma2(accA[0][0], aP.x, kp.x); fma2(accA[0][1], aP.x, kp.y);
            fma2(accA[1][0], aP.y, kp.x); fma2(accA[1][1], aP.y, kp.y);
            fma2(accY[0][0], aP.x, sp.x); fma2(accY[0][1], aP.x, sp.y);
            fma2(accY[1][0], aP.y, sp.x); fma2(accY[1][1], aP.y, sp.y);
            if (tx == 0) {
                const float z = sZ[dd];
                den0 += unpk(aP.x).x * z;
                den1 += unpk(aP.y).x * z;
            }
        }
        __syncthreads();
    }

    // mask + store A (duplicated pairs)
#pragma unroll
    for (int i = 0; i < 2; i++) {
        float2 p0 = unpk(accA[i][0]);
        float2 p1 = unpk(accA[i][1]);
        const int tl = ty2 + i;
        const int tg = rbase + tl;
        float m0 = (tx4 + 0 <= tg) ? p0.x : 0.f;
        float m1 = (tx4 + 1 <= tg) ? p0.y : 0.f;
        float m2 = (tx4 + 2 <= tg) ? p1.x : 0.f;
        float m3 = (tx4 + 3 <= tg) ? p1.y : 0.f;
        *(float2*)&sAd[tl][2 * (tx4 + 0)] = make_float2(m0, m0);
        *(float2*)&sAd[tl][2 * (tx4 + 1)] = make_float2(m1, m1);
        *(float2*)&sAd[tl][2 * (tx4 + 2)] = make_float2(m2, m2);
        *(float2*)&sAd[tl][2 * (tx4 + 3)] = make_float2(m3, m3);
    }
    __syncthreads();

    // Y += A @ V; only cols s < rbase+32 can be nonzero
    const int ns = rbase + 32;
#pragma unroll 4
    for (int s = 0; s < ns; s++) {
        ull a0 = *(const ull*)&sAd[ty2 + 0][2 * s];
        ull a1 = *(const ull*)&sAd[ty2 + 1][2 * s];
        ulonglong2 v = *(const ulonglong2*)&sV[s][tx4];
        fma2(accY[0][0], a0, v.x); fma2(accY[0][1], a0, v.y);
        fma2(accY[1][0], a1, v.x); fma2(accY[1][1], a1, v.y);
    }

    // den: add rowsums of masked A
    if (tx == 0) {
        float r0 = den0 + EPSV, r1 = den1 + EPSV;
#pragma unroll 8
        for (int s = 0; s < ns; s++) {
            r0 += sAd[ty2 + 0][2 * s];
            r1 += sAd[ty2 + 1][2 * s];
        }
        sDen[ty2 + 0] = r0; sDen[ty2 + 1] = r1;
    }
    __syncthreads();

    float* yo = &g_Y[(size_t)(c * CT + rbase) * DM + h * HD + tx4];
#pragma unroll
    for (int i = 0; i < 2; i++) {
        const float inv = 1.f / sDen[ty2 + i];
        float2 p0 = unpk(accY[i][0]);
        float2 p1 = unpk(accY[i][1]);
        float4 o;
        o.x = p0.x * inv; o.y = p0.y * inv; o.z = p1.x * inv; o.w = p1.y * inv;
        *(float4*)&yo[(size_t)(ty2 + i) * DM] = o;
    }
}

// ---------------------------------------------------------------------------
extern "C" void kernel_launch(void* const* d_in, const int* in_sizes, int n_in,
                              void* d_out, int out_size)
{
    const float* hs = (const float*)d_in[0];
    const float* Wq = (const float*)d_in[1];
    const float* Wk = (const float*)d_in[2];
    const float* Wv = (const float*)d_in[3];
    const float* Wo = (const float*)d_in[4];
    float* out = (float*)d_out;

    gemm_proj_fused<<<dim3(8, 18), 256>>>(hs, Wq, Wk, Wv);
    phi_kernel<<<LSEQ, DP>>>();
    chunk_kv_kernel<<<dim3(CH, NH), DP>>>();
    prefix_kernel<<<(NSLANE + NZLANE + 255) / 256, 256>>>();
    attn_out_kernel<<<dim3(CH, NH, 2), 256>>>();
    gemm_out_kernel<<<dim3(8, 12), 256>>>(Wo, out);
}

// round 12
// speedup vs baseline: 1.0102x; 1.0102x over previous
#include <cuda_runtime.h>

typedef unsigned long long ull;

// Problem constants
#define LSEQ 512
#define NH 12
#define FD 16
#define HD 64
#define DM 768
#define DREAL 273
#define DP 288          // padded feature dim (zeros in 273..287)
#define CH 8            // number of chunks
#define CT 64           // chunk length
#define PROJ_N 1152     // q(192) | k(192) | v(768)
#define EPSV 1e-12f
#define PHI_S 0.17677669529663687f   // 1/(4*sqrt(2))

// Scratch (device globals; no allocation allowed)
__device__ float g_P[LSEQ * PROJ_N];            // projection output
__device__ float g_phiQ[NH * LSEQ * DP];
__device__ float g_phiK[NH * LSEQ * DP];
__device__ float g_S[NH * CH * DP * HD];        // chunk KV sums -> exclusive prefix states
__device__ float g_Z[NH * CH * DP];             // chunk k sums  -> exclusive prefix
__device__ float g_Y[LSEQ * DM];                // attention output (pre-Wo)

// ---------------------------------------------------------------------------
// Packed f32x2 helpers
// ---------------------------------------------------------------------------
__device__ __forceinline__ ull dup2(float a) {
    ull r; asm("mov.b64 %0, {%1, %1};" : "=l"(r) : "f"(a)); return r;
}
__device__ __forceinline__ void fma2(ull& d, ull a, ull b) {
    asm("fma.rn.f32x2 %0, %1, %2, %0;" : "+l"(d) : "l"(a), "l"(b));
}
__device__ __forceinline__ float2 unpk(ull v) {
    float2 r; asm("mov.b64 {%0, %1}, %2;" : "=f"(r.x), "=f"(r.y) : "l"(v)); return r;
}

// ---------------------------------------------------------------------------
// Tiled fp32 GEMM, 128 threads, 32-row x 64-col tiles, BK=16, 4x4 microtile.
// C[row0+m, coff+n] = sum_k A[row0+m,k] * B[n,k]
// A operand stored DUPLICATED in smem so FFMA2 needs no broadcast movs.
// Same inner loop as the proven 256-thread version; more blocks -> 2+/SM.
// ---------------------------------------------------------------------------
__device__ __forceinline__ void gemm_body32(
    const float* __restrict__ A, const float* __restrict__ B,
    float* __restrict__ C, int K, int ldc, int coff, int row0)
{
    __shared__ __align__(16) float As2[2][16][68];    // [k][2*row(32)] dup pairs
    __shared__ __align__(16) float Bs[2][16][68];
    const int tid = threadIdx.x;
    const int tx = tid & 15, ty = tid >> 4;           // tx 0..15, ty 0..7
    const int ty8 = ty * 8, tx4 = tx * 4;
    const int lr = tid >> 2;            // 0..31
    const int lk = (tid & 3) * 4;       // 0,4,8,12

    ull acc[4][2];
#pragma unroll
    for (int i = 0; i < 4; i++) { acc[i][0] = 0ull; acc[i][1] = 0ull; }

    const float* ap = &A[(size_t)(row0 + lr) * K + lk];      // 32 A rows
    const float* bp0 = &B[(size_t)lr * K + lk];              // B rows lr, lr+32
    const float* bp1 = &B[(size_t)(lr + 32) * K + lk];

    {
        float4 av = *(const float4*)ap;
        float4 b0 = *(const float4*)bp0;
        float4 b1 = *(const float4*)bp1;
        *(float2*)&As2[0][lk + 0][2 * lr] = make_float2(av.x, av.x);
        *(float2*)&As2[0][lk + 1][2 * lr] = make_float2(av.y, av.y);
        *(float2*)&As2[0][lk + 2][2 * lr] = make_float2(av.z, av.z);
        *(float2*)&As2[0][lk + 3][2 * lr] = make_float2(av.w, av.w);
        Bs[0][lk + 0][lr] = b0.x; Bs[0][lk + 1][lr] = b0.y;
        Bs[0][lk + 2][lr] = b0.z; Bs[0][lk + 3][lr] = b0.w;
        Bs[0][lk + 0][lr + 32] = b1.x; Bs[0][lk + 1][lr + 32] = b1.y;
        Bs[0][lk + 2][lr + 32] = b1.z; Bs[0][lk + 3][lr + 32] = b1.w;
    }
    __syncthreads();

    int buf = 0;
    for (int k0 = 0; k0 < K; k0 += 16) {
        float4 av2, b02, b12;
        const bool more = (k0 + 16 < K);
        if (more) {
            av2 = *(const float4*)(ap + k0 + 16);
            b02 = *(const float4*)(bp0 + k0 + 16);
            b12 = *(const float4*)(bp1 + k0 + 16);
        }
#pragma unroll
        for (int kk = 0; kk < 16; kk++) {
            ulonglong2 aP = *(const ulonglong2*)&As2[buf][kk][ty8];
            ulonglong2 aQ = *(const ulonglong2*)&As2[buf][kk][ty8 + 4];
            ulonglong2 b  = *(const ulonglong2*)&Bs[buf][kk][tx4];
            fma2(acc[0][0], aP.x, b.x); fma2(acc[0][1], aP.x, b.y);
            fma2(acc[1][0], aP.y, b.x); fma2(acc[1][1], aP.y, b.y);
            fma2(acc[2][0], aQ.x, b.x); fma2(acc[2][1], aQ.x, b.y);
            fma2(acc[3][0], aQ.y, b.x); fma2(acc[3][1], aQ.y, b.y);
        }
        if (more) {
            const int nb = buf ^ 1;
            *(float2*)&As2[nb][lk + 0][2 * lr] = make_float2(av2.x, av2.x);
            *(float2*)&As2[nb][lk + 1][2 * lr] = make_float2(av2.y, av2.y);
            *(float2*)&As2[nb][lk + 2][2 * lr] = make_float2(av2.z, av2.z);
            *(float2*)&As2[nb][lk + 3][2 * lr] = make_float2(av2.w, av2.w);
            Bs[nb][lk + 0][lr] = b02.x; Bs[nb][lk + 1][lr] = b02.y;
            Bs[nb][lk + 2][lr] = b02.z; Bs[nb][lk + 3][lr] = b02.w;
            Bs[nb][lk + 0][lr + 32] = b12.x; Bs[nb][lk + 1][lr + 32] = b12.y;
            Bs[nb][lk + 2][lr + 32] = b12.z; Bs[nb][lk + 3][lr + 32] = b12.w;
        }
        __syncthreads();
        buf ^= 1;
    }

    // rows: ty*4 + i covers 0..31 (8 ty values x 4)
#pragma unroll
    for (int i = 0; i < 4; i++) {
        float2 p0 = unpk(acc[i][0]);
        float2 p1 = unpk(acc[i][1]);
        float4 o; o.x = p0.x; o.y = p0.y; o.z = p1.x; o.w = p1.y;
        *(float4*)&C[(size_t)(row0 + ty * 4 + i) * ldc + coff + tx4] = o;
    }
}

// Fused q|k|v projection: grid (16, 18), 128 threads
__global__ __launch_bounds__(128) void gemm_proj_fused(
    const float* __restrict__ hs, const float* __restrict__ Wq,
    const float* __restrict__ Wk, const float* __restrict__ Wv)
{
    const int cb = blockIdx.y;
    const float* B; int coff;
    if (cb < 3)      { B = Wq + (size_t)cb * 64 * DM;        coff = cb * 64; }
    else if (cb < 6) { B = Wk + (size_t)(cb - 3) * 64 * DM;  coff = 192 + (cb - 3) * 64; }
    else             { B = Wv + (size_t)(cb - 6) * 64 * DM;  coff = 384 + (cb - 6) * 64; }
    gemm_body32(hs, B, g_P, DM, PROJ_N, coff, blockIdx.x * 32);
}

// Output projection: grid (16, 12), 128 threads
__global__ __launch_bounds__(128) void gemm_out_kernel(
    const float* __restrict__ Wo, float* __restrict__ out)
{
    gemm_body32(g_Y, Wo + (size_t)blockIdx.y * 64 * DM, out, DM, DM,
                blockIdx.y * 64, blockIdx.x * 32);
}

// ---------------------------------------------------------------------------
// Taylor feature map: phi = [1, x/2, x_i*x_j/(4*sqrt(2))], padded with zeros.
// grid (512), 288 threads — each block handles one sequence position, all heads
// ---------------------------------------------------------------------------
__global__ void phi_kernel()
{
    const int l = blockIdx.x, d = threadIdx.x;
    __shared__ float sx[384];
    for (int i = d; i < 384; i += 288) sx[i] = g_P[(size_t)l * PROJ_N + i];
    __syncthreads();

    int ii = 0, jj = 0, mode;
    if (d == 0) mode = 0;
    else if (d <= 16) { mode = 1; ii = d - 1; }
    else if (d < DREAL) { mode = 2; const int e = d - 17; ii = e >> 4; jj = e & 15; }
    else mode = 3;

    const size_t base = (size_t)l * DP + d;
#pragma unroll
    for (int h = 0; h < NH; h++) {
        const float* xq = &sx[h * FD];
        const float* xk = &sx[192 + h * FD];
        float vq, vk;
        if (mode == 0)      { vq = 1.f; vk = 1.f; }
        else if (mode == 1) { vq = xq[ii] * 0.5f; vk = xk[ii] * 0.5f; }
        else if (mode == 2) { vq = xq[ii] * xq[jj] * PHI_S; vk = xk[ii] * xk[jj] * PHI_S; }
        else                { vq = 0.f; vk = 0.f; }
        g_phiQ[(size_t)h * LSEQ * DP + base] = vq;
        g_phiK[(size_t)h * LSEQ * DP + base] = vk;
    }
}

// ---------------------------------------------------------------------------
// Per-chunk local sums: S_local[d][j] = sum_t phiK[t][d]*V[t][j]; z[d]=sum_t phiK
// grid (CH, NH), 288 threads (one per feature d), packed FFMA2
// ---------------------------------------------------------------------------
__global__ void chunk_kv_kernel()
{
    const int c = blockIdx.x, h = blockIdx.y;
    __shared__ __align__(16) float sV[CT][68];
    const int tid = threadIdx.x;
    for (int idx = tid; idx < CT * HD; idx += 288) {
        const int t = idx >> 6, j = idx & 63;
        sV[t][j] = g_P[(size_t)(c * CT + t) * PROJ_N + 384 + h * HD + j];
    }
    __syncthreads();

    const int d = tid;      // 0..287
    ull acc[32];
#pragma unroll
    for (int i = 0; i < 32; i++) acc[i] = 0ull;
    float zs = 0.f;

    const float* pk = &g_phiK[(size_t)(h * LSEQ + c * CT) * DP + d];
#pragma unroll 2
    for (int t = 0; t < CT; t++) {
        const float kd = pk[(size_t)t * DP];
        zs += kd;
        const ull kdp = dup2(kd);
#pragma unroll
        for (int j = 0; j < 16; j++) {
            ulonglong2 v = *(const ulonglong2*)&sV[t][j * 4];
            fma2(acc[2 * j + 0], kdp, v.x);
            fma2(acc[2 * j + 1], kdp, v.y);
        }
    }
    float* outp = &g_S[((size_t)(h * CH + c) * DP + d) * HD];
#pragma unroll
    for (int j = 0; j < 16; j++) {
        float2 p0 = unpk(acc[2 * j + 0]);
        float2 p1 = unpk(acc[2 * j + 1]);
        float4 o; o.x = p0.x; o.y = p0.y; o.z = p1.x; o.w = p1.y;
        *(float4*)&outp[j * 4] = o;
    }
    g_Z[(size_t)(h * CH + c) * DP + d] = zs;
}

// ---------------------------------------------------------------------------
// Merged parallel exclusive prefix over chunks (S lanes then Z lanes).
// ---------------------------------------------------------------------------
#define NSLANE (NH * DP * HD)
#define NZLANE (NH * DP)
__global__ __launch_bounds__(256) void prefix_kernel()
{
    const int idx = blockIdx.x * 256 + threadIdx.x;
    if (idx < NSLANE) {
        const int h = idx / (DP * HD);
        const int r = idx - h * (DP * HD);
        const size_t base = (size_t)h * CH * DP * HD + r;
        float v[CH];
#pragma unroll
        for (int c = 0; c < CH; c++) v[c] = g_S[base + (size_t)c * DP * HD];
        float carry = 0.f;
#pragma unroll
        for (int c = 0; c < CH; c++) {
            g_S[base + (size_t)c * DP * HD] = carry;
            carry += v[c];
        }
    } else if (idx < NSLANE + NZLANE) {
        const int z = idx - NSLANE;
        const int h = z / DP;
        const int d = z - h * DP;
        const size_t base = (size_t)h * CH * DP + d;
        float v[CH];
#pragma unroll
        for (int c = 0; c < CH; c++) v[c] = g_Z[base + (size_t)c * DP];
        float carry = 0.f;
#pragma unroll
        for (int c = 0; c < CH; c++) {
            g_Z[base + (size_t)c * DP] = carry;
            carry += v[c];
        }
    }
}

// ---------------------------------------------------------------------------
// Per-chunk attention output — R4 monolithic layout + double-buffered tiles:
//   A = tril(phiQ phiK^T);  Y = phiQ @ S_prev + A @ V
//   den = phiQ . z_prev + rowsum(A) + eps;  y = Y / den
// grid (CH, NH), 256 threads, 4x4 microtile, ONE barrier per feature tile.
// ---------------------------------------------------------------------------
__global__ __launch_bounds__(256) void attn_out_kernel()
{
    const int c = blockIdx.x, h = blockIdx.y;
    __shared__ __align__(16) float sAd[CT][132];      // masked A, duplicated pairs
    __shared__ __align__(16) float sV[CT][68];
    __shared__ __align__(16) float sQt2[2][16][132];  // [feature][2*row] duplicated
    __shared__ __align__(16) float sKt[2][16][68];
    __shared__ __align__(16) float sS[2][16][68];
    __shared__ float sZ[2][16];
    __shared__ float sDen[CT];

    const int tid = threadIdx.x;
    const int tx = tid & 15, ty = tid >> 4;
    const int ty4 = ty * 4, tx4 = tx * 4, ty8 = ty * 8;
    const int lr = tid >> 2;
    const int lc = (tid & 3) * 4;

    // load V chunk
    for (int idx = tid; idx < CT * HD; idx += 256) {
        const int t = idx >> 6, j = idx & 63;
        sV[t][j] = g_P[(size_t)(c * CT + t) * PROJ_N + 384 + h * HD + j];
    }

    const float* phq = &g_phiQ[(size_t)(h * LSEQ + c * CT) * DP];
    const float* phk = &g_phiK[(size_t)(h * LSEQ + c * CT) * DP];
    const float* Sp = &g_S[(size_t)(h * CH + c) * DP * HD];
    const float* Zp = &g_Z[(size_t)(h * CH + c) * DP];

    ull accA[4][2], accY[4][2];
#pragma unroll
    for (int i = 0; i < 4; i++) {
        accA[i][0] = 0ull; accA[i][1] = 0ull;
        accY[i][0] = 0ull; accY[i][1] = 0ull;
    }
    float den0 = 0.f, den1 = 0.f, den2 = 0.f, den3 = 0.f;

    // S tile lane mapping: 16 feats x 16 col-groups
    const int sd = tid >> 4, sj = (tid & 15) * 4;

    // prefetch + commit tile 0 into buffer 0
    {
        float4 qv = *(const float4*)&phq[(size_t)lr * DP + lc];
        float4 kv = *(const float4*)&phk[(size_t)lr * DP + lc];
        float4 sv = *(const float4*)&Sp[(size_t)sd * HD + sj];
        *(float2*)&sQt2[0][lc + 0][2 * lr] = make_float2(qv.x, qv.x);
        *(float2*)&sQt2[0][lc + 1][2 * lr] = make_float2(qv.y, qv.y);
        *(float2*)&sQt2[0][lc + 2][2 * lr] = make_float2(qv.z, qv.z);
        *(float2*)&sQt2[0][lc + 3][2 * lr] = make_float2(qv.w, qv.w);
        sKt[0][lc + 0][lr] = kv.x; sKt[0][lc + 1][lr] = kv.y;
        sKt[0][lc + 2][lr] = kv.z; sKt[0][lc + 3][lr] = kv.w;
        *(float4*)&sS[0][sd][sj] = sv;
        if (tid < 16) sZ[0][tid] = Zp[tid];
    }
    __syncthreads();

    for (int it = 0; it < DP / 16; it++) {
        const int b = it & 1;
        const int dn = (it + 1) * 16;
        const bool more = (dn < DP);
        float4 qv, kv, sv; float zv = 0.f;
        if (more) {
            qv = *(const float4*)&phq[(size_t)lr * DP + dn + lc];
            kv = *(const float4*)&phk[(size_t)lr * DP + dn + lc];
            sv = *(const float4*)&Sp[(size_t)(dn + sd) * HD + sj];
            if (tid < 16) zv = Zp[dn + tid];
        }

#pragma unroll
        for (int dd = 0; dd < 16; dd++) {
            ulonglong2 aP = *(const ulonglong2*)&sQt2[b][dd][ty8];
            ulonglong2 aQ = *(const ulonglong2*)&sQt2[b][dd][ty8 + 4];
            ulonglong2 kp = *(const ulonglong2*)&sKt[b][dd][tx4];
            ulonglong2 sp = *(const ulonglong2*)&sS[b][dd][tx4];
            fma2(accA[0][0], aP.x, kp.x); fma2(accA[0][1], aP.x, kp.y);
            fma2(accA[1][0], aP.y, kp.x); fma2(accA[1][1], aP.y, kp.y);
            fma2(accA[2][0], aQ.x, kp.x); fma2(accA[2][1], aQ.x, kp.y);
            fma2(accA[3][0], aQ.y, kp.x); fma2(accA[3][1], aQ.y, kp.y);
            fma2(accY[0][0], aP.x, sp.x); fma2(accY[0][1], aP.x, sp.y);
            fma2(accY[1][0], aP.y, sp.x); fma2(accY[1][1], aP.y, sp.y);
            fma2(accY[2][0], aQ.x, sp.x); fma2(accY[2][1], aQ.x, sp.y);
            fma2(accY[3][0], aQ.y, sp.x); fma2(accY[3][1], aQ.y, sp.y);
            if (tx == 0) {
                const float z = sZ[b][dd];
                den0 += unpk(aP.x).x * z; den1 += unpk(aP.y).x * z;
                den2 += unpk(aQ.x).x * z; den3 += unpk(aQ.y).x * z;
            }
        }

        if (more) {     // commit next tile into the other buffer (safe: last
            const int nb = b ^ 1;   // reader of nb finished before prev barrier)
            *(float2*)&sQt2[nb][lc + 0][2 * lr] = make_float2(qv.x, qv.x);
            *(float2*)&sQt2[nb][lc + 1][2 * lr] = make_float2(qv.y, qv.y);
            *(float2*)&sQt2[nb][lc + 2][2 * lr] = make_float2(qv.z, qv.z);
            *(float2*)&sQt2[nb][lc + 3][2 * lr] = make_float2(qv.w, qv.w);
            sKt[nb][lc + 0][lr] = kv.x; sKt[nb][lc + 1][lr] = kv.y;
            sKt[nb][lc + 2][lr] = kv.z; sKt[nb][lc + 3][lr] = kv.w;
            *(float4*)&sS[nb][sd][sj] = sv;
            if (tid < 16) sZ[nb][tid] = zv;
        }
        __syncthreads();
    }

    // mask + store A (duplicated pairs for FFMA2 A.V loop)
#pragma unroll
    for (int i = 0; i < 4; i++) {
        float2 p0 = unpk(accA[i][0]);
        float2 p1 = unpk(accA[i][1]);
        const int t = ty4 + i;
        float m0 = (tx4 + 0 <= t) ? p0.x : 0.f;
        float m1 = (tx4 + 1 <= t) ? p0.y : 0.f;
        float m2 = (tx4 + 2 <= t) ? p1.x : 0.f;
        float m3 = (tx4 + 3 <= t) ? p1.y : 0.f;
        *(float2*)&sAd[t][2 * (tx4 + 0)] = make_float2(m0, m0);
        *(float2*)&sAd[t][2 * (tx4 + 1)] = make_float2(m1, m1);
        *(float2*)&sAd[t][2 * (tx4 + 2)] = make_float2(m2, m2);
        *(float2*)&sAd[t][2 * (tx4 + 3)] = make_float2(m3, m3);
    }
    __syncthreads();

    // Y += A @ V (A masked, duplicated)
#pragma unroll 4
    for (int s = 0; s < CT; s++) {
        ull a0 = *(const ull*)&sAd[ty4 + 0][2 * s];
        ull a1 = *(const ull*)&sAd[ty4 + 1][2 * s];
        ull a2 = *(const ull*)&sAd[ty4 + 2][2 * s];
        ull a3 = *(const ull*)&sAd[ty4 + 3][2 * s];
        ulonglong2 v = *(const ulonglong2*)&sV[s][tx4];
        fma2(accY[0][0], a0, v.x); fma2(accY[0][1], a0, v.y);
        fma2(accY[1][0], a1, v.x); fma2(accY[1][1], a1, v.y);
        fma2(accY[2][0], a2, v.x); fma2(accY[2][1], a2, v.y);
        fma2(accY[3][0], a3, v.x); fma2(accY[3][1], a3, v.y);
    }

    // den: add rowsums of masked A
    if (tx == 0) {
        float r0 = den0 + EPSV, r1 = den1 + EPSV, r2 = den2 + EPSV, r3 = den3 + EPSV;
#pragma unroll 8
        for (int s = 0; s < CT; s++) {
            r0 += sAd[ty4 + 0][2 * s];
            r1 += sAd[ty4 + 1][2 * s];
            r2 += sAd[ty4 + 2][2 * s];
            r3 += sAd[ty4 + 3][2 * s];
        }
        sDen[ty4 + 0] = r0; sDen[ty4 + 1] = r1; sDen[ty4 + 2] = r2; sDen[ty4 + 3] = r3;
    }
    __syncthreads();

    float* yo = &g_Y[(size_t)(c * CT) * DM + h * HD + tx4];
#pragma unroll
    for (int i = 0; i < 4; i++) {
        const float inv = 1.f / sDen[ty4 + i];
        float2 p0 = unpk(accY[i][0]);
        float2 p1 = unpk(accY[i][1]);
        float4 o;
        o.x = p0.x * inv; o.y = p0.y * inv; o.z = p1.x * inv; o.w = p1.y * inv;
        *(float4*)&yo[(size_t)(ty4 + i) * DM] = o;
    }
}

// ---------------------------------------------------------------------------
extern "C" void kernel_launch(void* const* d_in, const int* in_sizes, int n_in,
                              void* d_out, int out_size)
{
    const float* hs = (const float*)d_in[0];
    const float* Wq = (const float*)d_in[1];
    const float* Wk = (const float*)d_in[2];
    const float* Wv = (const float*)d_in[3];
    const float* Wo = (const float*)d_in[4];
    float* out = (float*)d_out;

    gemm_proj_fused<<<dim3(16, 18), 128>>>(hs, Wq, Wk, Wv);
    phi_kernel<<<LSEQ, DP>>>();
    chunk_kv_kernel<<<dim3(CH, NH), DP>>>();
    prefix_kernel<<<(NSLANE + NZLANE + 255) / 256, 256>>>();
    attn_out_kernel<<<dim3(CH, NH), 256>>>();
    gemm_out_kernel<<<dim3(16, 12), 128>>>(Wo, out);
}